// round 5
// baseline (speedup 1.0000x reference)
#include <cuda_runtime.h>
#include <cstdint>

#define Dm 512
#define Sq 512
#define Bz 4
#define Hh 8
#define FF 2048
#define NL 6
#define TOK (Bz*Sq)        // 2048 tokens
#define NEGV (-1000000000.0f)

// ---------------- scratch (no allocations allowed) ----------------
__device__ float g_Q  [TOK*Dm];
__device__ float g_K  [TOK*Dm];
__device__ float g_V  [TOK*Dm];
__device__ float g_Sc [Bz*Hh*Sq*Sq];   // 32 MB attention scores
__device__ float g_Ctx[TOK*Dm];
__device__ float g_Tmp[TOK*Dm];
__device__ float g_Ffn[TOK*FF];
__device__ float g_Enc[TOK*Dm];
__device__ float g_Dec[TOK*Dm];

// ---------------- PTX helpers ----------------
__device__ __forceinline__ uint32_t smem_u32(const void* p) {
    return (uint32_t)__cvta_generic_to_shared(p);
}
__device__ __forceinline__ void cpasync16(uint32_t dst, const void* src) {
    asm volatile("cp.async.cg.shared.global [%0], [%1], 16;\n" :: "r"(dst), "l"(src));
}
__device__ __forceinline__ void cp_commit() { asm volatile("cp.async.commit_group;\n"); }
template<int N> __device__ __forceinline__ void cp_wait() {
    asm volatile("cp.async.wait_group %0;\n" :: "n"(N));
}
// D += A(16x8) * B(8x8), tf32 inputs (HW truncates raw fp32 bits), fp32 accum
__device__ __forceinline__ void mma8(float* c, const uint32_t* a, const uint32_t* b) {
    asm volatile("mma.sync.aligned.m16n8k8.row.col.f32.tf32.tf32.f32 "
                 "{%0,%1,%2,%3},{%4,%5,%6,%7},{%8,%9},{%0,%1,%2,%3};\n"
                 : "+f"(c[0]), "+f"(c[1]), "+f"(c[2]), "+f"(c[3])
                 : "r"(a[0]), "r"(a[1]), "r"(a[2]), "r"(a[3]), "r"(b[0]), "r"(b[1]));
}
// cheap split: hi = top-10-mantissa truncation (what the MMA keeps), lo = exact residue
__device__ __forceinline__ void split_tf32(float x, uint32_t& hi, uint32_t& lo) {
    uint32_t h = __float_as_uint(x) & 0xFFFFE000u;
    hi = h;
    lo = __float_as_uint(x - __uint_as_float(h));
}
__device__ __forceinline__ float2 split_pair(float x) {
    uint32_t h, l; split_tf32(x, h, l);
    return make_float2(__uint_as_float(h), __uint_as_float(l));
}
// C += A*B with 3 mmas: lo*hi + hi*lo + hi*hi
__device__ __forceinline__ void mma3(float* c, const uint32_t* ah, const uint32_t* al,
                                     const uint32_t* bh, const uint32_t* bl) {
    mma8(c, al, bh);
    mma8(c, ah, bl);
    mma8(c, ah, bh);
}

// ================= main GEMM: C[M,N] = A[M,K] @ B[K,N] =================
// 128x64 block, BK=16, 4 warps (64x32 warp tiles).
// Smem holds pre-split (hi,lo) pairs; inner loop is pure LDS.64 + HMMA.
#define BM 128
#define BN 64
#define BK 16
#define AS2 40    // words per A row: 16 k * 2 + 8 pad; 40 % 32 == 8 -> conflict-free
#define BS2 136   // words per B row: 64 n * 2 + 8 pad; 136 % 32 == 8 -> conflict-free

template<bool RELU>
__device__ __forceinline__ void gemm_body(
    const float* __restrict__ A, const float* __restrict__ B,
    float* __restrict__ C, int M, int N, int K) {
    __shared__ float As[BM * AS2];
    __shared__ float Bs[BK * BS2];
    const int t = threadIdx.x;
    const int warp = t >> 5, lane = t & 31, g = lane >> 2, tg = lane & 3;
    const int wm = (warp & 1) * 64, wn = (warp >> 1) * 32;
    const int rowBase = blockIdx.y * BM, colBase = blockIdx.x * BN;
    const int am = t >> 2, ak = (t & 3) * 4;   // A: 32 rows/pass, 4 passes
    const int bk = t >> 4, bn = (t & 15) * 4;  // B: 8 rows/pass, 2 passes

    float4 aR[4], bR[2];
    float c[4][4][4] = {};

    auto load_tile = [&](int k0) {
        #pragma unroll
        for (int i = 0; i < 4; i++)
            aR[i] = *(const float4*)&A[(size_t)(rowBase + am + i * 32) * K + k0 + ak];
        #pragma unroll
        for (int i = 0; i < 2; i++)
            bR[i] = *(const float4*)&B[(size_t)(k0 + bk + i * 8) * N + colBase + bn];
    };
    auto store_split = [&]() {
        #pragma unroll
        for (int i = 0; i < 4; i++) {
            const float v[4] = {aR[i].x, aR[i].y, aR[i].z, aR[i].w};
            #pragma unroll
            for (int j = 0; j < 4; j++)
                *(float2*)&As[(am + i * 32) * AS2 + (ak + j) * 2] = split_pair(v[j]);
        }
        #pragma unroll
        for (int i = 0; i < 2; i++) {
            const float v[4] = {bR[i].x, bR[i].y, bR[i].z, bR[i].w};
            #pragma unroll
            for (int j = 0; j < 4; j++)
                *(float2*)&Bs[(bk + i * 8) * BS2 + (bn + j) * 2] = split_pair(v[j]);
        }
    };

    const int iters = K / BK;
    load_tile(0);
    for (int i = 0; i < iters; i++) {
        store_split();
        __syncthreads();
        if (i + 1 < iters) load_tile((i + 1) * BK);   // LDG latency hidden by compute
        #pragma unroll
        for (int kk = 0; kk < BK; kk += 8) {
            uint32_t ah[4][4], al[4][4], bh[4][2], bl[4][2];
            #pragma unroll
            for (int mt = 0; mt < 4; mt++) {
                const float* base = &As[(wm + mt * 16) * AS2 + kk * 2];
                float2 p0 = *(const float2*)&base[g * AS2 + tg * 2];
                float2 p1 = *(const float2*)&base[(g + 8) * AS2 + tg * 2];
                float2 p2 = *(const float2*)&base[g * AS2 + (tg + 4) * 2];
                float2 p3 = *(const float2*)&base[(g + 8) * AS2 + (tg + 4) * 2];
                ah[mt][0] = __float_as_uint(p0.x); al[mt][0] = __float_as_uint(p0.y);
                ah[mt][1] = __float_as_uint(p1.x); al[mt][1] = __float_as_uint(p1.y);
                ah[mt][2] = __float_as_uint(p2.x); al[mt][2] = __float_as_uint(p2.y);
                ah[mt][3] = __float_as_uint(p3.x); al[mt][3] = __float_as_uint(p3.y);
            }
            #pragma unroll
            for (int nt = 0; nt < 4; nt++) {
                const float* base = &Bs[kk * BS2 + (wn + nt * 8 + g) * 2];
                float2 p0 = *(const float2*)&base[tg * BS2];
                float2 p1 = *(const float2*)&base[(tg + 4) * BS2];
                bh[nt][0] = __float_as_uint(p0.x); bl[nt][0] = __float_as_uint(p0.y);
                bh[nt][1] = __float_as_uint(p1.x); bl[nt][1] = __float_as_uint(p1.y);
            }
            #pragma unroll
            for (int mt = 0; mt < 4; mt++)
                #pragma unroll
                for (int nt = 0; nt < 4; nt++)
                    mma3(c[mt][nt], ah[mt], al[mt], bh[nt], bl[nt]);
        }
        __syncthreads();
    }
    // epilogue
    #pragma unroll
    for (int mt = 0; mt < 4; mt++) {
        #pragma unroll
        for (int nt = 0; nt < 4; nt++) {
            int r0 = rowBase + wm + mt * 16 + g;
            int col = colBase + wn + nt * 8 + tg * 2;
            float2 v0 = {c[mt][nt][0], c[mt][nt][1]};
            float2 v1 = {c[mt][nt][2], c[mt][nt][3]};
            if (RELU) {
                v0.x = fmaxf(v0.x, 0.f); v0.y = fmaxf(v0.y, 0.f);
                v1.x = fmaxf(v1.x, 0.f); v1.y = fmaxf(v1.y, 0.f);
            }
            *(float2*)&C[(size_t)r0 * N + col] = v0;
            *(float2*)&C[(size_t)(r0 + 8) * N + col] = v1;
        }
    }
}

template<bool RELU>
__global__ __launch_bounds__(128) void gemm_tf32(
    const float* __restrict__ A, const float* __restrict__ B,
    float* __restrict__ C, int M, int N, int K) {
    gemm_body<RELU>(A, B, C, M, N, K);
}

// merged QKV projections: blockIdx.z selects {A, B, C} triple
struct Triple { const float* A[3]; const float* B[3]; float* C[3]; };
__global__ __launch_bounds__(128) void gemm_qkv(Triple tp, int M, int N, int K) {
    const int z = blockIdx.z;
    gemm_body<false>(tp.A[z], tp.B[z], tp.C[z], M, N, K);
}

// ============ scores[bh,q,c] = (Q[b,q,h,:] . K[b,c,h,:]) / 8 ============
#define QSTR 68
__global__ __launch_bounds__(128) void scores_tf32(
    const float* __restrict__ Q, const float* __restrict__ Kx, float* __restrict__ S) {
    __shared__ float Qs[64 * QSTR];
    __shared__ float Ks[64 * QSTR];
    const int bh = blockIdx.z, b = bh >> 3, h = bh & 7;
    const int q0 = blockIdx.y * 64, c0 = blockIdx.x * 64;
    const int t = threadIdx.x;
    const int warp = t >> 5, lane = t & 31, g = lane >> 2, tg = lane & 3;
    const int wm = (warp & 1) * 32, wn = (warp >> 1) * 32;
    const int lr = t >> 4, ld4 = (t & 15) * 4;

    #pragma unroll
    for (int i = 0; i < 8; i++) {
        int r = lr + i * 8;
        cpasync16(smem_u32(&Qs[r * QSTR + ld4]),
                  &Q[(size_t)((b * Sq + q0 + r) * Dm) + h * 64 + ld4]);
        cpasync16(smem_u32(&Ks[r * QSTR + ld4]),
                  &Kx[(size_t)((b * Sq + c0 + r) * Dm) + h * 64 + ld4]);
    }
    cp_commit(); cp_wait<0>();
    __syncthreads();

    float c[2][4][4] = {};
    #pragma unroll
    for (int kk = 0; kk < 64; kk += 8) {
        uint32_t ah[2][4], al[2][4], bh[4][2], bl[4][2];
        #pragma unroll
        for (int mt = 0; mt < 2; mt++) {
            const float* base = &Qs[(wm + mt * 16) * QSTR + kk];
            split_tf32(base[g * QSTR + tg],           ah[mt][0], al[mt][0]);
            split_tf32(base[(g + 8) * QSTR + tg],     ah[mt][1], al[mt][1]);
            split_tf32(base[g * QSTR + tg + 4],       ah[mt][2], al[mt][2]);
            split_tf32(base[(g + 8) * QSTR + tg + 4], ah[mt][3], al[mt][3]);
        }
        #pragma unroll
        for (int nt = 0; nt < 4; nt++) {
            const float* base = &Ks[(wn + nt * 8 + g) * QSTR + kk];
            split_tf32(base[tg],     bh[nt][0], bl[nt][0]);
            split_tf32(base[tg + 4], bh[nt][1], bl[nt][1]);
        }
        #pragma unroll
        for (int mt = 0; mt < 2; mt++)
            #pragma unroll
            for (int nt = 0; nt < 4; nt++)
                mma3(c[mt][nt], ah[mt], al[mt], bh[nt], bl[nt]);
    }
    #pragma unroll
    for (int mt = 0; mt < 2; mt++)
        #pragma unroll
        for (int nt = 0; nt < 4; nt++) {
            int r0 = q0 + wm + mt * 16 + g;
            int col = c0 + wn + nt * 8 + tg * 2;
            float2 v0 = {c[mt][nt][0] * 0.125f, c[mt][nt][1] * 0.125f};
            float2 v1 = {c[mt][nt][2] * 0.125f, c[mt][nt][3] * 0.125f};
            *(float2*)&S[(size_t)(bh * Sq + r0) * Sq + col] = v0;
            *(float2*)&S[(size_t)(bh * Sq + r0 + 8) * Sq + col] = v1;
        }
}

// ============ ctx[b,q,h,:] = P[bh] @ V[b,:,h,:]  (512x64, K=512) ============
#define PSTR 68
#define VSTR 72
__global__ __launch_bounds__(128) void ctx_tf32(
    const float* __restrict__ P, const float* __restrict__ V, float* __restrict__ C) {
    __shared__ float Ps[64 * PSTR];
    __shared__ float Vs[64 * VSTR];
    const int bh = blockIdx.y, b = bh >> 3, h = bh & 7;
    const int q0 = blockIdx.x * 64;
    const int t = threadIdx.x;
    const int warp = t >> 5, lane = t & 31, g = lane >> 2, tg = lane & 3;
    const int wm = (warp & 1) * 32, wn = (warp >> 1) * 32;
    const int lr = t >> 4, ld4 = (t & 15) * 4;

    float c[2][4][4] = {};
    for (int k0 = 0; k0 < Sq; k0 += 64) {
        #pragma unroll
        for (int i = 0; i < 8; i++) {
            int r = lr + i * 8;
            cpasync16(smem_u32(&Ps[r * PSTR + ld4]),
                      &P[(size_t)(bh * Sq + q0 + r) * Sq + k0 + ld4]);
            cpasync16(smem_u32(&Vs[r * VSTR + ld4]),
                      &V[(size_t)((b * Sq + k0 + r) * Dm) + h * 64 + ld4]);
        }
        cp_commit(); cp_wait<0>();
        __syncthreads();
        #pragma unroll
        for (int kk = 0; kk < 64; kk += 8) {
            uint32_t ah[2][4], al[2][4], bh[4][2], bl[4][2];
            #pragma unroll
            for (int mt = 0; mt < 2; mt++) {
                const float* base = &Ps[(wm + mt * 16) * PSTR + kk];
                split_tf32(base[g * PSTR + tg],           ah[mt][0], al[mt][0]);
                split_tf32(base[(g + 8) * PSTR + tg],     ah[mt][1], al[mt][1]);
                split_tf32(base[g * PSTR + tg + 4],       ah[mt][2], al[mt][2]);
                split_tf32(base[(g + 8) * PSTR + tg + 4], ah[mt][3], al[mt][3]);
            }
            #pragma unroll
            for (int nt = 0; nt < 4; nt++) {
                const float* base = &Vs[kk * VSTR + wn + nt * 8 + g];
                split_tf32(base[tg * VSTR],       bh[nt][0], bl[nt][0]);
                split_tf32(base[(tg + 4) * VSTR], bh[nt][1], bl[nt][1]);
            }
            #pragma unroll
            for (int mt = 0; mt < 2; mt++)
                #pragma unroll
                for (int nt = 0; nt < 4; nt++)
                    mma3(c[mt][nt], ah[mt], al[mt], bh[nt], bl[nt]);
        }
        __syncthreads();
    }
    #pragma unroll
    for (int mt = 0; mt < 2; mt++)
        #pragma unroll
        for (int nt = 0; nt < 4; nt++) {
            int r0 = q0 + wm + mt * 16 + g;
            int col = h * 64 + wn + nt * 8 + tg * 2;
            *(float2*)&C[(size_t)((b * Sq + r0) * Dm) + col] =
                make_float2(c[mt][nt][0], c[mt][nt][1]);
            *(float2*)&C[(size_t)((b * Sq + r0 + 8) * Dm) + col] =
                make_float2(c[mt][nt][2], c[mt][nt][3]);
        }
}

// ---------------- row softmax over 512, optional mask ----------------
__global__ void softmax_kernel(float* __restrict__ S, const int* __restrict__ mask) {
    const int row = blockIdx.x;
    const int q = row & 511;
    const int bh = row >> 9;
    const int b = bh >> 3;
    float* p = S + (size_t)row * Sq;
    const int t = threadIdx.x;
    float v0 = p[t], v1 = p[t + 256];
    if (mask) {
        const int* mrow = mask + (size_t)(b * Sq + q) * Sq;
        if (mrow[t] == 0)       v0 = NEGV;
        if (mrow[t + 256] == 0) v1 = NEGV;
    }
    __shared__ float red[256];
    red[t] = fmaxf(v0, v1); __syncthreads();
    for (int s = 128; s > 0; s >>= 1) { if (t < s) red[t] = fmaxf(red[t], red[t + s]); __syncthreads(); }
    float m = red[0]; __syncthreads();
    float e0 = __expf(v0 - m), e1 = __expf(v1 - m);
    red[t] = e0 + e1; __syncthreads();
    for (int s = 128; s > 0; s >>= 1) { if (t < s) red[t] += red[t + s]; __syncthreads(); }
    float inv = 1.0f / red[0];
    p[t] = e0 * inv; p[t + 256] = e1 * inv;
}

// ---------------- out = LayerNorm(X + R) ----------------
__global__ void add_ln_kernel(const float* __restrict__ X, const float* __restrict__ R,
                              float* __restrict__ O) {
    const int row = blockIdx.x;
    const int t = threadIdx.x;
    const float* x = X + (size_t)row * Dm;
    const float* r = R + (size_t)row * Dm;
    float v0 = x[t] + r[t], v1 = x[t + 256] + r[t + 256];
    __shared__ float red[256];
    red[t] = v0 + v1; __syncthreads();
    for (int s = 128; s > 0; s >>= 1) { if (t < s) red[t] += red[t + s]; __syncthreads(); }
    float mean = red[0] * (1.0f / Dm); __syncthreads();
    float d0 = v0 - mean, d1 = v1 - mean;
    red[t] = d0 * d0 + d1 * d1; __syncthreads();
    for (int s = 128; s > 0; s >>= 1) { if (t < s) red[t] += red[t + s]; __syncthreads(); }
    float inv = rsqrtf(red[0] * (1.0f / Dm) + 1e-5f);
    float* o = O + (size_t)row * Dm;
    o[t] = d0 * inv; o[t + 256] = d1 * inv;
}

// ---------------- host orchestration ----------------
struct Bufs { float *Q, *K, *V, *Sc, *Ctx, *Tmp, *Ffn, *Enc, *Dec; };

static void attn_block(const float* xq, const float* xkv,
                       const float* Wq, const float* Wk, const float* Wv, const float* Wo,
                       const int* mask, float* dst, const Bufs& bf) {
    dim3 gP(Dm / BN, TOK / BM);
    Triple tp;
    tp.A[0] = xq;  tp.A[1] = xkv; tp.A[2] = xkv;
    tp.B[0] = Wq;  tp.B[1] = Wk;  tp.B[2] = Wv;
    tp.C[0] = bf.Q; tp.C[1] = bf.K; tp.C[2] = bf.V;
    gemm_qkv<<<dim3(gP.x, gP.y, 3), 128>>>(tp, TOK, Dm, Dm);
    scores_tf32<<<dim3(Sq / 64, Sq / 64, Bz * Hh), 128>>>(bf.Q, bf.K, bf.Sc);
    softmax_kernel<<<Bz * Hh * Sq, 256>>>(bf.Sc, mask);
    ctx_tf32<<<dim3(Sq / 64, Bz * Hh), 128>>>(bf.Sc, bf.V, bf.Ctx);
    gemm_tf32<false><<<gP, 128>>>(bf.Ctx, Wo, bf.Tmp, TOK, Dm, Dm);
    add_ln_kernel<<<TOK, 256>>>(bf.Tmp, xq, dst);
}

static void ffn_block(const float* x, const float* W1, const float* W2,
                      float* dst, const Bufs& bf) {
    gemm_tf32<true ><<<dim3(FF / BN, TOK / BM), 128>>>(x, W1, bf.Ffn, TOK, FF, Dm);
    gemm_tf32<false><<<dim3(Dm / BN, TOK / BM), 128>>>(bf.Ffn, W2, bf.Tmp, TOK, Dm, FF);
    add_ln_kernel<<<TOK, 256>>>(bf.Tmp, x, dst);
}

extern "C" void kernel_launch(void* const* d_in, const int* in_sizes, int n_in,
                              void* d_out, int out_size) {
    const float* enc_in  = (const float*)d_in[0];
    const float* dec_in  = (const float*)d_in[1];
    const int*   mask    = (const int*)  d_in[2];
    const float* enc_Wq  = (const float*)d_in[3];
    const float* enc_Wk  = (const float*)d_in[4];
    const float* enc_Wv  = (const float*)d_in[5];
    const float* enc_Wo  = (const float*)d_in[6];
    const float* enc_W1  = (const float*)d_in[7];
    const float* enc_W2  = (const float*)d_in[8];
    const float* sa_Wq   = (const float*)d_in[9];
    const float* sa_Wk   = (const float*)d_in[10];
    const float* sa_Wv   = (const float*)d_in[11];
    const float* sa_Wo   = (const float*)d_in[12];
    const float* ca_Wq   = (const float*)d_in[13];
    const float* ca_Wk   = (const float*)d_in[14];
    const float* ca_Wv   = (const float*)d_in[15];
    const float* ca_Wo   = (const float*)d_in[16];
    const float* dec_W1  = (const float*)d_in[17];
    const float* dec_W2  = (const float*)d_in[18];

    Bufs bf;
    cudaGetSymbolAddress((void**)&bf.Q,   g_Q);
    cudaGetSymbolAddress((void**)&bf.K,   g_K);
    cudaGetSymbolAddress((void**)&bf.V,   g_V);
    cudaGetSymbolAddress((void**)&bf.Sc,  g_Sc);
    cudaGetSymbolAddress((void**)&bf.Ctx, g_Ctx);
    cudaGetSymbolAddress((void**)&bf.Tmp, g_Tmp);
    cudaGetSymbolAddress((void**)&bf.Ffn, g_Ffn);
    cudaGetSymbolAddress((void**)&bf.Enc, g_Enc);
    cudaGetSymbolAddress((void**)&bf.Dec, g_Dec);

    const size_t WP  = (size_t)Dm * Dm;
    const size_t W1S = (size_t)Dm * FF;
    const size_t W2S = (size_t)FF * Dm;

    // ---- encoder stack ----
    const float* src = enc_in;
    for (int i = 0; i < NL; i++) {
        attn_block(src, src, enc_Wq + i * WP, enc_Wk + i * WP, enc_Wv + i * WP,
                   enc_Wo + i * WP, nullptr, bf.Enc, bf);
        ffn_block(bf.Enc, enc_W1 + i * W1S, enc_W2 + i * W2S, bf.Enc, bf);
        src = bf.Enc;
    }

    // ---- decoder stack ----
    const float* dsrc = dec_in;
    for (int i = 0; i < NL; i++) {
        attn_block(dsrc, dsrc, sa_Wq + i * WP, sa_Wk + i * WP, sa_Wv + i * WP,
                   sa_Wo + i * WP, mask, bf.Dec, bf);
        attn_block(bf.Dec, bf.Enc, ca_Wq + i * WP, ca_Wk + i * WP, ca_Wv + i * WP,
                   ca_Wo + i * WP, nullptr, bf.Dec, bf);
        float* out = (i == NL - 1) ? (float*)d_out : bf.Dec;
        ffn_block(bf.Dec, dec_W1 + i * W1S, dec_W2 + i * W2S, out, bf);
        dsrc = bf.Dec;
    }
}

// round 6
// speedup vs baseline: 1.0007x; 1.0007x over previous
#include <cuda_runtime.h>
#include <cstdint>

#define Dm 512
#define Sq 512
#define Bz 4
#define Hh 8
#define FF 2048
#define NL 6
#define TOK (Bz*Sq)        // 2048 tokens
#define NEGV (-1000000000.0f)

// ---------------- scratch (no allocations allowed) ----------------
__device__ float g_Q  [TOK*Dm];
__device__ float g_K  [TOK*Dm];
__device__ float g_V  [TOK*Dm];
__device__ float g_Sc [Bz*Hh*Sq*Sq];   // 32 MB attention scores
__device__ float g_Ctx[TOK*Dm];
__device__ float g_Tmp[TOK*Dm];
__device__ float g_Ffn[TOK*FF];
__device__ float g_Enc[TOK*Dm];
__device__ float g_Dec[TOK*Dm];

// ---------------- PTX helpers ----------------
__device__ __forceinline__ uint32_t smem_u32(const void* p) {
    return (uint32_t)__cvta_generic_to_shared(p);
}
__device__ __forceinline__ void cpasync16(uint32_t dst, const void* src) {
    asm volatile("cp.async.cg.shared.global [%0], [%1], 16;\n" :: "r"(dst), "l"(src));
}
__device__ __forceinline__ void cp_commit() { asm volatile("cp.async.commit_group;\n"); }
template<int N> __device__ __forceinline__ void cp_wait() {
    asm volatile("cp.async.wait_group %0;\n" :: "n"(N));
}
// D += A(16x8) * B(8x8), tf32 inputs (HW truncates raw fp32 bits), fp32 accum
__device__ __forceinline__ void mma8(float* c, const uint32_t* a, const uint32_t* b) {
    asm volatile("mma.sync.aligned.m16n8k8.row.col.f32.tf32.tf32.f32 "
                 "{%0,%1,%2,%3},{%4,%5,%6,%7},{%8,%9},{%0,%1,%2,%3};\n"
                 : "+f"(c[0]), "+f"(c[1]), "+f"(c[2]), "+f"(c[3])
                 : "r"(a[0]), "r"(a[1]), "r"(a[2]), "r"(a[3]), "r"(b[0]), "r"(b[1]));
}
// cheap split: hi = top-10-mantissa truncation (what the MMA keeps), lo = exact residue
__device__ __forceinline__ void split_tf32(float x, uint32_t& hi, uint32_t& lo) {
    uint32_t h = __float_as_uint(x) & 0xFFFFE000u;
    hi = h;
    lo = __float_as_uint(x - __uint_as_float(h));
}
__device__ __forceinline__ float2 split_pair(float x) {
    uint32_t h, l; split_tf32(x, h, l);
    return make_float2(__uint_as_float(h), __uint_as_float(l));
}
// C += A*B with 3 mmas: lo*hi + hi*lo + hi*hi
__device__ __forceinline__ void mma3(float* c, const uint32_t* ah, const uint32_t* al,
                                     const uint32_t* bh, const uint32_t* bl) {
    mma8(c, al, bh);
    mma8(c, ah, bl);
    mma8(c, ah, bh);
}

// ================= main GEMM: C[M,N] = A[M,K] @ B[K,N] =================
// 128x64 block, BK=16, 4 warps (64x32 warp tiles).
// Smem holds pre-split (hi,lo) pairs; inner loop is pure LDS.64 + HMMA.
#define BM 128
#define BN 64
#define BK 16
#define AS2 40    // words per A row: 16 k * 2 + 8 pad; 40 % 32 == 8 -> conflict-free
#define BS2 136   // words per B row: 64 n * 2 + 8 pad; 136 % 32 == 8 -> conflict-free

template<bool RELU>
__device__ __forceinline__ void gemm_body(
    const float* __restrict__ A, const float* __restrict__ B,
    float* __restrict__ C, int M, int N, int K) {
    __shared__ float As[BM * AS2];
    __shared__ float Bs[BK * BS2];
    const int t = threadIdx.x;
    const int warp = t >> 5, lane = t & 31, g = lane >> 2, tg = lane & 3;
    const int wm = (warp & 1) * 64, wn = (warp >> 1) * 32;
    const int rowBase = blockIdx.y * BM, colBase = blockIdx.x * BN;
    const int am = t >> 2, ak = (t & 3) * 4;   // A: 32 rows/pass, 4 passes
    const int bk = t >> 4, bn = (t & 15) * 4;  // B: 8 rows/pass, 2 passes

    float4 aR[4], bR[2];
    float c[4][4][4] = {};

    auto load_tile = [&](int k0) {
        #pragma unroll
        for (int i = 0; i < 4; i++)
            aR[i] = *(const float4*)&A[(size_t)(rowBase + am + i * 32) * K + k0 + ak];
        #pragma unroll
        for (int i = 0; i < 2; i++)
            bR[i] = *(const float4*)&B[(size_t)(k0 + bk + i * 8) * N + colBase + bn];
    };
    auto store_split = [&]() {
        #pragma unroll
        for (int i = 0; i < 4; i++) {
            const float v[4] = {aR[i].x, aR[i].y, aR[i].z, aR[i].w};
            #pragma unroll
            for (int j = 0; j < 4; j++)
                *(float2*)&As[(am + i * 32) * AS2 + (ak + j) * 2] = split_pair(v[j]);
        }
        #pragma unroll
        for (int i = 0; i < 2; i++) {
            const float v[4] = {bR[i].x, bR[i].y, bR[i].z, bR[i].w};
            #pragma unroll
            for (int j = 0; j < 4; j++)
                *(float2*)&Bs[(bk + i * 8) * BS2 + (bn + j) * 2] = split_pair(v[j]);
        }
    };

    const int iters = K / BK;
    load_tile(0);
    for (int i = 0; i < iters; i++) {
        store_split();
        __syncthreads();
        if (i + 1 < iters) load_tile((i + 1) * BK);   // LDG latency hidden by compute
        #pragma unroll
        for (int kk = 0; kk < BK; kk += 8) {
            uint32_t ah[4][4], al[4][4], bh[4][2], bl[4][2];
            #pragma unroll
            for (int mt = 0; mt < 4; mt++) {
                const float* base = &As[(wm + mt * 16) * AS2 + kk * 2];
                float2 p0 = *(const float2*)&base[g * AS2 + tg * 2];
                float2 p1 = *(const float2*)&base[(g + 8) * AS2 + tg * 2];
                float2 p2 = *(const float2*)&base[g * AS2 + (tg + 4) * 2];
                float2 p3 = *(const float2*)&base[(g + 8) * AS2 + (tg + 4) * 2];
                ah[mt][0] = __float_as_uint(p0.x); al[mt][0] = __float_as_uint(p0.y);
                ah[mt][1] = __float_as_uint(p1.x); al[mt][1] = __float_as_uint(p1.y);
                ah[mt][2] = __float_as_uint(p2.x); al[mt][2] = __float_as_uint(p2.y);
                ah[mt][3] = __float_as_uint(p3.x); al[mt][3] = __float_as_uint(p3.y);
            }
            #pragma unroll
            for (int nt = 0; nt < 4; nt++) {
                const float* base = &Bs[kk * BS2 + (wn + nt * 8 + g) * 2];
                float2 p0 = *(const float2*)&base[tg * BS2];
                float2 p1 = *(const float2*)&base[(tg + 4) * BS2];
                bh[nt][0] = __float_as_uint(p0.x); bl[nt][0] = __float_as_uint(p0.y);
                bh[nt][1] = __float_as_uint(p1.x); bl[nt][1] = __float_as_uint(p1.y);
            }
            #pragma unroll
            for (int mt = 0; mt < 4; mt++)
                #pragma unroll
                for (int nt = 0; nt < 4; nt++)
                    mma3(c[mt][nt], ah[mt], al[mt], bh[nt], bl[nt]);
        }
        __syncthreads();
    }
    // epilogue
    #pragma unroll
    for (int mt = 0; mt < 4; mt++) {
        #pragma unroll
        for (int nt = 0; nt < 4; nt++) {
            int r0 = rowBase + wm + mt * 16 + g;
            int col = colBase + wn + nt * 8 + tg * 2;
            float2 v0 = {c[mt][nt][0], c[mt][nt][1]};
            float2 v1 = {c[mt][nt][2], c[mt][nt][3]};
            if (RELU) {
                v0.x = fmaxf(v0.x, 0.f); v0.y = fmaxf(v0.y, 0.f);
                v1.x = fmaxf(v1.x, 0.f); v1.y = fmaxf(v1.y, 0.f);
            }
            *(float2*)&C[(size_t)r0 * N + col] = v0;
            *(float2*)&C[(size_t)(r0 + 8) * N + col] = v1;
        }
    }
}

template<bool RELU>
__global__ __launch_bounds__(128) void gemm_tf32(
    const float* __restrict__ A, const float* __restrict__ B,
    float* __restrict__ C, int M, int N, int K) {
    gemm_body<RELU>(A, B, C, M, N, K);
}

// merged QKV projections: blockIdx.z selects {A, B, C} triple
struct Triple { const float* A[3]; const float* B[3]; float* C[3]; };
__global__ __launch_bounds__(128) void gemm_qkv(Triple tp, int M, int N, int K) {
    const int z = blockIdx.z;
    gemm_body<false>(tp.A[z], tp.B[z], tp.C[z], M, N, K);
}

// ============ scores[bh,q,c] = (Q[b,q,h,:] . K[b,c,h,:]) / 8 ============
#define QSTR 68
__global__ __launch_bounds__(128) void scores_tf32(
    const float* __restrict__ Q, const float* __restrict__ Kx, float* __restrict__ S) {
    __shared__ float Qs[64 * QSTR];
    __shared__ float Ks[64 * QSTR];
    const int bh = blockIdx.z, b = bh >> 3, h = bh & 7;
    const int q0 = blockIdx.y * 64, c0 = blockIdx.x * 64;
    const int t = threadIdx.x;
    const int warp = t >> 5, lane = t & 31, g = lane >> 2, tg = lane & 3;
    const int wm = (warp & 1) * 32, wn = (warp >> 1) * 32;
    const int lr = t >> 4, ld4 = (t & 15) * 4;

    #pragma unroll
    for (int i = 0; i < 8; i++) {
        int r = lr + i * 8;
        cpasync16(smem_u32(&Qs[r * QSTR + ld4]),
                  &Q[(size_t)((b * Sq + q0 + r) * Dm) + h * 64 + ld4]);
        cpasync16(smem_u32(&Ks[r * QSTR + ld4]),
                  &Kx[(size_t)((b * Sq + c0 + r) * Dm) + h * 64 + ld4]);
    }
    cp_commit(); cp_wait<0>();
    __syncthreads();

    float c[2][4][4] = {};
    #pragma unroll
    for (int kk = 0; kk < 64; kk += 8) {
        uint32_t ah[2][4], al[2][4], bh[4][2], bl[4][2];
        #pragma unroll
        for (int mt = 0; mt < 2; mt++) {
            const float* base = &Qs[(wm + mt * 16) * QSTR + kk];
            split_tf32(base[g * QSTR + tg],           ah[mt][0], al[mt][0]);
            split_tf32(base[(g + 8) * QSTR + tg],     ah[mt][1], al[mt][1]);
            split_tf32(base[g * QSTR + tg + 4],       ah[mt][2], al[mt][2]);
            split_tf32(base[(g + 8) * QSTR + tg + 4], ah[mt][3], al[mt][3]);
        }
        #pragma unroll
        for (int nt = 0; nt < 4; nt++) {
            const float* base = &Ks[(wn + nt * 8 + g) * QSTR + kk];
            split_tf32(base[tg],     bh[nt][0], bl[nt][0]);
            split_tf32(base[tg + 4], bh[nt][1], bl[nt][1]);
        }
        #pragma unroll
        for (int mt = 0; mt < 2; mt++)
            #pragma unroll
            for (int nt = 0; nt < 4; nt++)
                mma3(c[mt][nt], ah[mt], al[mt], bh[nt], bl[nt]);
    }
    #pragma unroll
    for (int mt = 0; mt < 2; mt++)
        #pragma unroll
        for (int nt = 0; nt < 4; nt++) {
            int r0 = q0 + wm + mt * 16 + g;
            int col = c0 + wn + nt * 8 + tg * 2;
            float2 v0 = {c[mt][nt][0] * 0.125f, c[mt][nt][1] * 0.125f};
            float2 v1 = {c[mt][nt][2] * 0.125f, c[mt][nt][3] * 0.125f};
            *(float2*)&S[(size_t)(bh * Sq + r0) * Sq + col] = v0;
            *(float2*)&S[(size_t)(bh * Sq + r0 + 8) * Sq + col] = v1;
        }
}

// ============ ctx[b,q,h,:] = P[bh] @ V[b,:,h,:]  (512x64, K=512) ============
#define PSTR 68
#define VSTR 72
__global__ __launch_bounds__(128) void ctx_tf32(
    const float* __restrict__ P, const float* __restrict__ V, float* __restrict__ C) {
    __shared__ float Ps[64 * PSTR];
    __shared__ float Vs[64 * VSTR];
    const int bh = blockIdx.y, b = bh >> 3, h = bh & 7;
    const int q0 = blockIdx.x * 64;
    const int t = threadIdx.x;
    const int warp = t >> 5, lane = t & 31, g = lane >> 2, tg = lane & 3;
    const int wm = (warp & 1) * 32, wn = (warp >> 1) * 32;
    const int lr = t >> 4, ld4 = (t & 15) * 4;

    float c[2][4][4] = {};
    for (int k0 = 0; k0 < Sq; k0 += 64) {
        #pragma unroll
        for (int i = 0; i < 8; i++) {
            int r = lr + i * 8;
            cpasync16(smem_u32(&Ps[r * PSTR + ld4]),
                      &P[(size_t)(bh * Sq + q0 + r) * Sq + k0 + ld4]);
            cpasync16(smem_u32(&Vs[r * VSTR + ld4]),
                      &V[(size_t)((b * Sq + k0 + r) * Dm) + h * 64 + ld4]);
        }
        cp_commit(); cp_wait<0>();
        __syncthreads();
        #pragma unroll
        for (int kk = 0; kk < 64; kk += 8) {
            uint32_t ah[2][4], al[2][4], bh[4][2], bl[4][2];
            #pragma unroll
            for (int mt = 0; mt < 2; mt++) {
                const float* base = &Ps[(wm + mt * 16) * PSTR + kk];
                split_tf32(base[g * PSTR + tg],           ah[mt][0], al[mt][0]);
                split_tf32(base[(g + 8) * PSTR + tg],     ah[mt][1], al[mt][1]);
                split_tf32(base[g * PSTR + tg + 4],       ah[mt][2], al[mt][2]);
                split_tf32(base[(g + 8) * PSTR + tg + 4], ah[mt][3], al[mt][3]);
            }
            #pragma unroll
            for (int nt = 0; nt < 4; nt++) {
                const float* base = &Vs[kk * VSTR + wn + nt * 8 + g];
                split_tf32(base[tg * VSTR],       bh[nt][0], bl[nt][0]);
                split_tf32(base[(tg + 4) * VSTR], bh[nt][1], bl[nt][1]);
            }
            #pragma unroll
            for (int mt = 0; mt < 2; mt++)
                #pragma unroll
                for (int nt = 0; nt < 4; nt++)
                    mma3(c[mt][nt], ah[mt], al[mt], bh[nt], bl[nt]);
        }
        __syncthreads();
    }
    #pragma unroll
    for (int mt = 0; mt < 2; mt++)
        #pragma unroll
        for (int nt = 0; nt < 4; nt++) {
            int r0 = q0 + wm + mt * 16 + g;
            int col = h * 64 + wn + nt * 8 + tg * 2;
            *(float2*)&C[(size_t)((b * Sq + r0) * Dm) + col] =
                make_float2(c[mt][nt][0], c[mt][nt][1]);
            *(float2*)&C[(size_t)((b * Sq + r0 + 8) * Dm) + col] =
                make_float2(c[mt][nt][2], c[mt][nt][3]);
        }
}

// ---------------- row softmax over 512, optional mask ----------------
__global__ void softmax_kernel(float* __restrict__ S, const int* __restrict__ mask) {
    const int row = blockIdx.x;
    const int q = row & 511;
    const int bh = row >> 9;
    const int b = bh >> 3;
    float* p = S + (size_t)row * Sq;
    const int t = threadIdx.x;
    float v0 = p[t], v1 = p[t + 256];
    if (mask) {
        const int* mrow = mask + (size_t)(b * Sq + q) * Sq;
        if (mrow[t] == 0)       v0 = NEGV;
        if (mrow[t + 256] == 0) v1 = NEGV;
    }
    __shared__ float red[256];
    red[t] = fmaxf(v0, v1); __syncthreads();
    for (int s = 128; s > 0; s >>= 1) { if (t < s) red[t] = fmaxf(red[t], red[t + s]); __syncthreads(); }
    float m = red[0]; __syncthreads();
    float e0 = __expf(v0 - m), e1 = __expf(v1 - m);
    red[t] = e0 + e1; __syncthreads();
    for (int s = 128; s > 0; s >>= 1) { if (t < s) red[t] += red[t + s]; __syncthreads(); }
    float inv = 1.0f / red[0];
    p[t] = e0 * inv; p[t + 256] = e1 * inv;
}

// ---------------- out = LayerNorm(X + R) ----------------
__global__ void add_ln_kernel(const float* __restrict__ X, const float* __restrict__ R,
                              float* __restrict__ O) {
    const int row = blockIdx.x;
    const int t = threadIdx.x;
    const float* x = X + (size_t)row * Dm;
    const float* r = R + (size_t)row * Dm;
    float v0 = x[t] + r[t], v1 = x[t + 256] + r[t + 256];
    __shared__ float red[256];
    red[t] = v0 + v1; __syncthreads();
    for (int s = 128; s > 0; s >>= 1) { if (t < s) red[t] += red[t + s]; __syncthreads(); }
    float mean = red[0] * (1.0f / Dm); __syncthreads();
    float d0 = v0 - mean, d1 = v1 - mean;
    red[t] = d0 * d0 + d1 * d1; __syncthreads();
    for (int s = 128; s > 0; s >>= 1) { if (t < s) red[t] += red[t + s]; __syncthreads(); }
    float inv = rsqrtf(red[0] * (1.0f / Dm) + 1e-5f);
    float* o = O + (size_t)row * Dm;
    o[t] = d0 * inv; o[t + 256] = d1 * inv;
}

// ---------------- host orchestration ----------------
struct Bufs { float *Q, *K, *V, *Sc, *Ctx, *Tmp, *Ffn, *Enc, *Dec; };

static void attn_block(const float* xq, const float* xkv,
                       const float* Wq, const float* Wk, const float* Wv, const float* Wo,
                       const int* mask, float* dst, const Bufs& bf) {
    dim3 gP(Dm / BN, TOK / BM);
    Triple tp;
    tp.A[0] = xq;  tp.A[1] = xkv; tp.A[2] = xkv;
    tp.B[0] = Wq;  tp.B[1] = Wk;  tp.B[2] = Wv;
    tp.C[0] = bf.Q; tp.C[1] = bf.K; tp.C[2] = bf.V;
    gemm_qkv<<<dim3(gP.x, gP.y, 3), 128>>>(tp, TOK, Dm, Dm);
    scores_tf32<<<dim3(Sq / 64, Sq / 64, Bz * Hh), 128>>>(bf.Q, bf.K, bf.Sc);
    softmax_kernel<<<Bz * Hh * Sq, 256>>>(bf.Sc, mask);
    ctx_tf32<<<dim3(Sq / 64, Bz * Hh), 128>>>(bf.Sc, bf.V, bf.Ctx);
    gemm_tf32<false><<<gP, 128>>>(bf.Ctx, Wo, bf.Tmp, TOK, Dm, Dm);
    add_ln_kernel<<<TOK, 256>>>(bf.Tmp, xq, dst);
}

static void ffn_block(const float* x, const float* W1, const float* W2,
                      float* dst, const Bufs& bf) {
    gemm_tf32<true ><<<dim3(FF / BN, TOK / BM), 128>>>(x, W1, bf.Ffn, TOK, FF, Dm);
    gemm_tf32<false><<<dim3(Dm / BN, TOK / BM), 128>>>(bf.Ffn, W2, bf.Tmp, TOK, Dm, FF);
    add_ln_kernel<<<TOK, 256>>>(bf.Tmp, x, dst);
}

extern "C" void kernel_launch(void* const* d_in, const int* in_sizes, int n_in,
                              void* d_out, int out_size) {
    const float* enc_in  = (const float*)d_in[0];
    const float* dec_in  = (const float*)d_in[1];
    const int*   mask    = (const int*)  d_in[2];
    const float* enc_Wq  = (const float*)d_in[3];
    const float* enc_Wk  = (const float*)d_in[4];
    const float* enc_Wv  = (const float*)d_in[5];
    const float* enc_Wo  = (const float*)d_in[6];
    const float* enc_W1  = (const float*)d_in[7];
    const float* enc_W2  = (const float*)d_in[8];
    const float* sa_Wq   = (const float*)d_in[9];
    const float* sa_Wk   = (const float*)d_in[10];
    const float* sa_Wv   = (const float*)d_in[11];
    const float* sa_Wo   = (const float*)d_in[12];
    const float* ca_Wq   = (const float*)d_in[13];
    const float* ca_Wk   = (const float*)d_in[14];
    const float* ca_Wv   = (const float*)d_in[15];
    const float* ca_Wo   = (const float*)d_in[16];
    const float* dec_W1  = (const float*)d_in[17];
    const float* dec_W2  = (const float*)d_in[18];

    Bufs bf;
    cudaGetSymbolAddress((void**)&bf.Q,   g_Q);
    cudaGetSymbolAddress((void**)&bf.K,   g_K);
    cudaGetSymbolAddress((void**)&bf.V,   g_V);
    cudaGetSymbolAddress((void**)&bf.Sc,  g_Sc);
    cudaGetSymbolAddress((void**)&bf.Ctx, g_Ctx);
    cudaGetSymbolAddress((void**)&bf.Tmp, g_Tmp);
    cudaGetSymbolAddress((void**)&bf.Ffn, g_Ffn);
    cudaGetSymbolAddress((void**)&bf.Enc, g_Enc);
    cudaGetSymbolAddress((void**)&bf.Dec, g_Dec);

    const size_t WP  = (size_t)Dm * Dm;
    const size_t W1S = (size_t)Dm * FF;
    const size_t W2S = (size_t)FF * Dm;

    // ---- encoder stack ----
    const float* src = enc_in;
    for (int i = 0; i < NL; i++) {
        attn_block(src, src, enc_Wq + i * WP, enc_Wk + i * WP, enc_Wv + i * WP,
                   enc_Wo + i * WP, nullptr, bf.Enc, bf);
        ffn_block(bf.Enc, enc_W1 + i * W1S, enc_W2 + i * W2S, bf.Enc, bf);
        src = bf.Enc;
    }

    // ---- decoder stack ----
    const float* dsrc = dec_in;
    for (int i = 0; i < NL; i++) {
        attn_block(dsrc, dsrc, sa_Wq + i * WP, sa_Wk + i * WP, sa_Wv + i * WP,
                   sa_Wo + i * WP, mask, bf.Dec, bf);
        attn_block(bf.Dec, bf.Enc, ca_Wq + i * WP, ca_Wk + i * WP, ca_Wv + i * WP,
                   ca_Wo + i * WP, nullptr, bf.Dec, bf);
        float* out = (i == NL - 1) ? (float*)d_out : bf.Dec;
        ffn_block(bf.Dec, dec_W1 + i * W1S, dec_W2 + i * W2S, out, bf);
        dsrc = bf.Dec;
    }
}